// round 1
// baseline (speedup 1.0000x reference)
#include <cuda_runtime.h>

#define BATCH   128
#define NANCH   8732
#define NCLS    21
#define NLOG    (4 + NCLS)
#define MAXOUT  5
#define NEGV    (-1e9f)
#define NMS_THREADS 512

// Scratch (device globals; no allocations allowed)
__device__ float g_boxes[BATCH * NANCH * 4];   // [B,N,4] y0,x0,y1,x1
__device__ float g_scores[BATCH * NANCH];      // effective scores (NEG for background)
__device__ float g_cls[BATCH * NANCH];         // argmax class as float

// ---------------------------------------------------------------------------
// Kernel 1: decode boxes + softmax max/argmax. One thread per (b, n).
// ---------------------------------------------------------------------------
__global__ void decode_kernel(const float* __restrict__ logits,
                              const float* __restrict__ db) {
    int gid = blockIdx.x * blockDim.x + threadIdx.x;
    if (gid >= BATCH * NANCH) return;
    int n = gid % NANCH;

    const float* L = logits + (size_t)gid * NLOG;
    float l0 = L[0], l1 = L[1], l2 = L[2], l3 = L[3];

    float cl[NCLS];
#pragma unroll
    for (int c = 0; c < NCLS; c++) cl[c] = L[4 + c];

    // argmax (first occurrence on ties, matching jnp.argmax)
    float best = cl[0];
    int   bi   = 0;
#pragma unroll
    for (int c = 1; c < NCLS; c++) {
        if (cl[c] > best) { best = cl[c]; bi = c; }
    }
    // max softmax prob = 1 / sum(exp(l - lmax))
    float sum = 0.f;
#pragma unroll
    for (int c = 0; c < NCLS; c++) sum += __expf(cl[c] - best);
    float score = 1.0f / sum;

    // decode: default box corners -> center/size
    const float4 d = *((const float4*)db + n);   // y0,x0,y1,x1
    float cy = 0.5f * (d.z + d.x);
    float cx = 0.5f * (d.w + d.y);
    float h  = d.z - d.x;
    float w  = d.w - d.y;
    float ncy = l0 * h + cy;
    float ncx = l1 * w + cx;
    float nh  = __expf(l2) * h;
    float nw  = __expf(l3) * w;
    float y0 = fminf(fmaxf(ncy - 0.5f * nh, 0.f), 1.f);
    float x0 = fminf(fmaxf(ncx - 0.5f * nw, 0.f), 1.f);
    float y1 = fminf(fmaxf(ncy + 0.5f * nh, 0.f), 1.f);
    float x1 = fminf(fmaxf(ncx + 0.5f * nw, 0.f), 1.f);

    ((float4*)g_boxes)[gid] = make_float4(y0, x0, y1, x1);
    g_scores[gid] = (bi != 0) ? score : NEGV;   // background masked out
    g_cls[gid]    = (float)bi;
}

// ---------------------------------------------------------------------------
// Kernel 2: per-batch sequential NMS, one block per batch element.
// Scores live in SMEM; argmax uses a packed u64 key:
//   high 32 bits = order-preserving float bits, low 32 bits = NANCH - i
// so max-reduce picks highest score, ties -> smallest index (== jnp.argmax).
// ---------------------------------------------------------------------------
__global__ void __launch_bounds__(NMS_THREADS)
nms_kernel(float* __restrict__ out) {
    __shared__ float s_sc[NANCH];
    __shared__ unsigned long long s_red[NMS_THREADS / 32];

    int b   = blockIdx.x;
    int tid = threadIdx.x;

    const float4* bx  = (const float4*)g_boxes + (size_t)b * NANCH;
    const float*  scg = g_scores + (size_t)b * NANCH;

    for (int i = tid; i < NANCH; i += NMS_THREADS) s_sc[i] = scg[i];
    __syncthreads();

    for (int t = 0; t < MAXOUT; t++) {
        // ---- block argmax ----
        unsigned long long bp = 0ull;
        for (int i = tid; i < NANCH; i += NMS_THREADS) {
            unsigned u = __float_as_uint(s_sc[i]);
            u = (u & 0x80000000u) ? ~u : (u | 0x80000000u);
            unsigned long long p =
                ((unsigned long long)u << 32) | (unsigned)(NANCH - i);
            if (p > bp) bp = p;
        }
#pragma unroll
        for (int off = 16; off > 0; off >>= 1) {
            unsigned long long o = __shfl_down_sync(0xffffffffu, bp, off);
            if (o > bp) bp = o;
        }
        if ((tid & 31) == 0) s_red[tid >> 5] = bp;
        __syncthreads();
        if (tid < 32) {
            unsigned long long v =
                (tid < NMS_THREADS / 32) ? s_red[tid] : 0ull;
#pragma unroll
            for (int off = 16; off > 0; off >>= 1) {
                unsigned long long o = __shfl_down_sync(0xffffffffu, v, off);
                if (o > v) v = o;
            }
            if (tid == 0) s_red[0] = v;
        }
        __syncthreads();
        bp = s_red[0];

        int idx = NANCH - (int)(bp & 0xFFFFFFFFu);
        unsigned su = (unsigned)(bp >> 32);
        // invert order-preserving map to recover the exact score bits
        float sc = __uint_as_float((su & 0x80000000u) ? (su & 0x7FFFFFFFu)
                                                      : ~su);
        float4 B = bx[idx];
        float a1 = (B.z - B.x) * (B.w - B.y);

        // ---- suppression (includes the selected box itself, IoU = 1) ----
        for (int i = tid; i < NANCH; i += NMS_THREADS) {
            float4 C = bx[i];
            float ty  = fmaxf(B.x, C.x);
            float tx  = fmaxf(B.y, C.y);
            float by  = fminf(B.z, C.z);
            float bxr = fminf(B.w, C.w);
            float hh  = fmaxf(by - ty, 0.f);
            float ww  = fmaxf(bxr - tx, 0.f);
            float inter = hh * ww;
            float a2 = (C.z - C.x) * (C.w - C.y);
            float iou = inter / (a1 + a2 - inter + 1e-12f);
            if (iou > 0.5f) s_sc[i] = NEGV;
        }

        if (tid == 0) {
            bool valid = sc > 0.5f;   // strict, matches reference
            float* o = out + ((size_t)b * MAXOUT + t) * 6;
            o[0] = valid ? B.x : 0.f;
            o[1] = valid ? B.y : 0.f;
            o[2] = valid ? B.z : 0.f;
            o[3] = valid ? B.w : 0.f;
            o[4] = valid ? g_cls[(size_t)b * NANCH + idx] : 0.f;
            o[5] = valid ? sc : 0.f;
        }
        __syncthreads();   // suppression + output done before next argmax
    }
}

// ---------------------------------------------------------------------------
extern "C" void kernel_launch(void* const* d_in, const int* in_sizes, int n_in,
                              void* d_out, int out_size) {
    const float* logits = (const float*)d_in[0];   // [128, 8732, 25]
    const float* db     = (const float*)d_in[1];   // [8732, 4]
    float*       out    = (float*)d_out;           // [128, 5, 6]

    int total = BATCH * NANCH;
    int threads = 256;
    int blocks  = (total + threads - 1) / threads;
    decode_kernel<<<blocks, threads>>>(logits, db);
    nms_kernel<<<BATCH, NMS_THREADS>>>(out);
}

// round 2
// speedup vs baseline: 2.4515x; 2.4515x over previous
#include <cuda_runtime.h>

#define BATCH   128
#define NANCH   8732
#define NCLS    21
#define NLOG    25
#define MAXOUT  5
#define CONF    0.5f
#define DEC_T   128
#define NMS_T   256

// Candidate lists (device globals; no allocation allowed).
__device__ int                 g_cnt[BATCH];
__device__ float4              g_cbox[BATCH * NANCH];
__device__ unsigned long long  g_ckey[BATCH * NANCH];
__device__ float               g_ccls[BATCH * NANCH];

__global__ void zero_counters() {
    if (threadIdx.x < BATCH) g_cnt[threadIdx.x] = 0;
}

// ---------------------------------------------------------------------------
// Decode + softmax-max/argmax + candidate compaction.
// One block = 128 anchors; logits tile staged through smem with coalesced
// float4 loads. smem reads at stride 25 are bank-conflict-free (gcd(25,32)=1).
// Only anchors with class!=0 AND score>0.5 can ever produce (or influence)
// a valid detection, so only those are kept.
// ---------------------------------------------------------------------------
__global__ void __launch_bounds__(DEC_T)
decode_kernel(const float* __restrict__ logits, const float* __restrict__ db) {
    __shared__ float tile[DEC_T * NLOG];

    long long base = (long long)blockIdx.x * DEC_T;        // global anchor id
    const float4* src = (const float4*)(logits + base * NLOG);
    float4* dst = (float4*)tile;
#pragma unroll
    for (int i = threadIdx.x; i < DEC_T * NLOG / 4; i += DEC_T) dst[i] = src[i];
    __syncthreads();

    int gid = (int)base + threadIdx.x;
    const float* L = tile + threadIdx.x * NLOG;

    // class argmax (first occurrence on ties)
    float best = L[4];
    int   bi   = 0;
#pragma unroll
    for (int c = 1; c < NCLS; c++) {
        float v = L[4 + c];
        if (v > best) { best = v; bi = c; }
    }
    float sum = 0.f;
#pragma unroll
    for (int c = 0; c < NCLS; c++) sum += __expf(L[4 + c] - best);
    float score = 1.0f / sum;

    if (bi != 0 && score > CONF) {
        int b = gid / NANCH;
        int n = gid % NANCH;
        float4 d = ((const float4*)db)[n];                 // y0,x0,y1,x1
        float cy = 0.5f * (d.z + d.x);
        float cx = 0.5f * (d.w + d.y);
        float h  = d.z - d.x;
        float w  = d.w - d.y;
        float ncy = L[0] * h + cy;
        float ncx = L[1] * w + cx;
        float nh  = __expf(L[2]) * h;
        float nw  = __expf(L[3]) * w;
        float4 box;
        box.x = fminf(fmaxf(ncy - 0.5f * nh, 0.f), 1.f);
        box.y = fminf(fmaxf(ncx - 0.5f * nw, 0.f), 1.f);
        box.z = fminf(fmaxf(ncy + 0.5f * nh, 0.f), 1.f);
        box.w = fminf(fmaxf(ncx + 0.5f * nw, 0.f), 1.f);

        int slot = atomicAdd(&g_cnt[b], 1);
        size_t o = (size_t)b * NANCH + slot;
        // key: [score bits (positive -> |0x80000000)] [NANCH-n : 14b][slot:14b]
        unsigned hi = __float_as_uint(score) | 0x80000000u;
        unsigned lo = ((unsigned)(NANCH - n) << 14) | (unsigned)slot;
        g_ckey[o] = ((unsigned long long)hi << 32) | lo;
        g_cbox[o] = box;
        g_ccls[o] = (float)bi;
    }
}

// ---------------------------------------------------------------------------
// NMS over the compacted candidate list. One block per batch element.
// All candidate scores > 0.5, so any selected candidate is valid; once the
// list is exhausted (bp==0), remaining output slots are zeros.
// ---------------------------------------------------------------------------
__global__ void __launch_bounds__(NMS_T)
nms_kernel(float* __restrict__ out) {
    __shared__ unsigned long long s_key[NANCH];
    __shared__ unsigned long long s_red[NMS_T / 32];

    int b   = blockIdx.x;
    int tid = threadIdx.x;
    int M   = g_cnt[b];

    const float4* cb = g_cbox + (size_t)b * NANCH;

    for (int i = tid; i < M; i += NMS_T)
        s_key[i] = g_ckey[(size_t)b * NANCH + i];
    __syncthreads();

    for (int t = 0; t < MAXOUT; t++) {
        // ---- block argmax over surviving candidates ----
        unsigned long long bp = 0ull;
        for (int i = tid; i < M; i += NMS_T) {
            unsigned long long k = s_key[i];
            if (k > bp) bp = k;
        }
#pragma unroll
        for (int off = 16; off > 0; off >>= 1) {
            unsigned long long o = __shfl_down_sync(0xffffffffu, bp, off);
            if (o > bp) bp = o;
        }
        if ((tid & 31) == 0) s_red[tid >> 5] = bp;
        __syncthreads();
        if (tid < 32) {
            unsigned long long v = (tid < NMS_T / 32) ? s_red[tid] : 0ull;
#pragma unroll
            for (int off = 16; off > 0; off >>= 1) {
                unsigned long long o = __shfl_down_sync(0xffffffffu, v, off);
                if (o > v) v = o;
            }
            if (tid == 0) s_red[0] = v;
        }
        __syncthreads();
        bp = s_red[0];

        if (bp == 0ull) {
            // no surviving candidate: all remaining slots are zeros
            if (tid == 0) {
                for (int tt = t; tt < MAXOUT; tt++) {
                    float* o = out + ((size_t)b * MAXOUT + tt) * 6;
                    o[0] = o[1] = o[2] = o[3] = o[4] = o[5] = 0.f;
                }
            }
            break;
        }

        int pos = (int)(bp & 0x3FFFull);
        float sc = __uint_as_float((unsigned)(bp >> 32) & 0x7FFFFFFFu);
        float4 B = cb[pos];
        float a1 = (B.z - B.x) * (B.w - B.y);

        // ---- suppression (selected box suppresses itself, IoU = 1) ----
        for (int i = tid; i < M; i += NMS_T) {
            if (s_key[i]) {
                float4 C = cb[i];
                float ty  = fmaxf(B.x, C.x);
                float tx  = fmaxf(B.y, C.y);
                float by  = fminf(B.z, C.z);
                float bxr = fminf(B.w, C.w);
                float hh  = fmaxf(by - ty, 0.f);
                float ww  = fmaxf(bxr - tx, 0.f);
                float inter = hh * ww;
                float a2 = (C.z - C.x) * (C.w - C.y);
                float iou = inter / (a1 + a2 - inter + 1e-12f);
                if (iou > 0.5f) s_key[i] = 0ull;
            }
        }

        if (tid == 0) {
            float* o = out + ((size_t)b * MAXOUT + t) * 6;
            o[0] = B.x; o[1] = B.y; o[2] = B.z; o[3] = B.w;
            o[4] = g_ccls[(size_t)b * NANCH + pos];
            o[5] = sc;
        }
        __syncthreads();
    }
}

// ---------------------------------------------------------------------------
extern "C" void kernel_launch(void* const* d_in, const int* in_sizes, int n_in,
                              void* d_out, int out_size) {
    const float* logits = (const float*)d_in[0];   // [128, 8732, 25]
    const float* db     = (const float*)d_in[1];   // [8732, 4]
    float*       out    = (float*)d_out;           // [128, 5, 6]

    zero_counters<<<1, 128>>>();
    decode_kernel<<<BATCH * NANCH / DEC_T, DEC_T>>>(logits, db);
    nms_kernel<<<BATCH, NMS_T>>>(out);
}

// round 3
// speedup vs baseline: 2.6000x; 1.0606x over previous
#include <cuda_runtime.h>

#define BATCH   128
#define NANCH   8732
#define NCLS    21
#define NLOG    25
#define MAXOUT  5
#define CONF    0.5f
#define DEC_T   128
#define NMS_T   256

// Candidate lists (device globals; zero-initialized at module load).
// g_cnt is restored to zero by nms_kernel at the end of every launch, so the
// sequence is self-consistent across graph replays with no reset kernel.
__device__ int                 g_cnt[BATCH];
__device__ float4              g_cbox[BATCH * NANCH];
__device__ unsigned long long  g_ckey[BATCH * NANCH];
__device__ float               g_ccls[BATCH * NANCH];

// ---------------------------------------------------------------------------
// Decode + softmax-max/argmax + candidate compaction.
// One block = 128 anchors; logits tile staged through smem with coalesced
// float4 loads, front-batched (7 independent LDGs in flight -> MLP=7).
// smem reads at stride 25 are bank-conflict-free (gcd(25,32)=1).
// Only anchors with class!=0 AND score>0.5 can ever produce (or influence)
// a valid detection, so only those are kept.
// ---------------------------------------------------------------------------
__global__ void __launch_bounds__(DEC_T)
decode_kernel(const float* __restrict__ logits, const float* __restrict__ db) {
    __shared__ float tile[DEC_T * NLOG];
    const int NV = DEC_T * NLOG / 4;                       // 800 float4

    long long base = (long long)blockIdx.x * DEC_T;        // global anchor id
    const float4* __restrict__ src = (const float4*)(logits + base * NLOG);
    float4* dst = (float4*)tile;

    // front-batched loads: 7 independent LDG.128 per thread, then stores
    float4 v[7];
    int tid = threadIdx.x;
#pragma unroll
    for (int k = 0; k < 7; k++) {
        int i = tid + k * DEC_T;
        if (i < NV) v[k] = src[i];
    }
#pragma unroll
    for (int k = 0; k < 7; k++) {
        int i = tid + k * DEC_T;
        if (i < NV) dst[i] = v[k];
    }
    __syncthreads();

    int gid = (int)base + tid;
    const float* L = tile + tid * NLOG;

    // class argmax (first occurrence on ties)
    float best = L[4];
    int   bi   = 0;
#pragma unroll
    for (int c = 1; c < NCLS; c++) {
        float vv = L[4 + c];
        if (vv > best) { best = vv; bi = c; }
    }
    float sum = 0.f;
#pragma unroll
    for (int c = 0; c < NCLS; c++) sum += __expf(L[4 + c] - best);
    float score = 1.0f / sum;

    if (bi != 0 && score > CONF) {
        int b = gid / NANCH;
        int n = gid % NANCH;
        float4 d = ((const float4*)db)[n];                 // y0,x0,y1,x1
        float cy = 0.5f * (d.z + d.x);
        float cx = 0.5f * (d.w + d.y);
        float h  = d.z - d.x;
        float w  = d.w - d.y;
        float ncy = L[0] * h + cy;
        float ncx = L[1] * w + cx;
        float nh  = __expf(L[2]) * h;
        float nw  = __expf(L[3]) * w;
        float4 box;
        box.x = fminf(fmaxf(ncy - 0.5f * nh, 0.f), 1.f);
        box.y = fminf(fmaxf(ncx - 0.5f * nw, 0.f), 1.f);
        box.z = fminf(fmaxf(ncy + 0.5f * nh, 0.f), 1.f);
        box.w = fminf(fmaxf(ncx + 0.5f * nw, 0.f), 1.f);

        int slot = atomicAdd(&g_cnt[b], 1);
        size_t o = (size_t)b * NANCH + slot;
        // key: [score bits (positive -> |0x80000000)] [NANCH-n : 14b][slot:14b]
        unsigned hi = __float_as_uint(score) | 0x80000000u;
        unsigned lo = ((unsigned)(NANCH - n) << 14) | (unsigned)slot;
        g_ckey[o] = ((unsigned long long)hi << 32) | lo;
        g_cbox[o] = box;
        g_ccls[o] = (float)bi;
    }
}

// ---------------------------------------------------------------------------
// NMS over the compacted candidate list. One block per batch element.
// All candidate scores > 0.5, so any selected candidate is valid; once the
// list is exhausted (bp==0), remaining output slots are zeros.
// Also restores g_cnt[b] = 0 for the next launch.
// ---------------------------------------------------------------------------
__global__ void __launch_bounds__(NMS_T)
nms_kernel(float* __restrict__ out) {
    __shared__ unsigned long long s_key[NANCH];
    __shared__ unsigned long long s_red[NMS_T / 32];

    int b   = blockIdx.x;
    int tid = threadIdx.x;
    int M   = g_cnt[b];                     // broadcast load by all threads

    const float4* __restrict__ cb = g_cbox + (size_t)b * NANCH;

    for (int i = tid; i < M; i += NMS_T)
        s_key[i] = g_ckey[(size_t)b * NANCH + i];
    __syncthreads();                        // all threads have read g_cnt[b]

    if (tid == 0) g_cnt[b] = 0;             // reset for next launch

    for (int t = 0; t < MAXOUT; t++) {
        // ---- block argmax over surviving candidates ----
        unsigned long long bp = 0ull;
        for (int i = tid; i < M; i += NMS_T) {
            unsigned long long k = s_key[i];
            if (k > bp) bp = k;
        }
#pragma unroll
        for (int off = 16; off > 0; off >>= 1) {
            unsigned long long o = __shfl_down_sync(0xffffffffu, bp, off);
            if (o > bp) bp = o;
        }
        if ((tid & 31) == 0) s_red[tid >> 5] = bp;
        __syncthreads();
        if (tid < 32) {
            unsigned long long vv = (tid < NMS_T / 32) ? s_red[tid] : 0ull;
#pragma unroll
            for (int off = 16; off > 0; off >>= 1) {
                unsigned long long o = __shfl_down_sync(0xffffffffu, vv, off);
                if (o > vv) vv = o;
            }
            if (tid == 0) s_red[0] = vv;
        }
        __syncthreads();
        bp = s_red[0];

        if (bp == 0ull) {
            // no surviving candidate: all remaining slots are zeros
            if (tid == 0) {
                for (int tt = t; tt < MAXOUT; tt++) {
                    float* o = out + ((size_t)b * MAXOUT + tt) * 6;
                    o[0] = o[1] = o[2] = o[3] = o[4] = o[5] = 0.f;
                }
            }
            break;
        }

        int pos = (int)(bp & 0x3FFFull);
        float sc = __uint_as_float((unsigned)(bp >> 32) & 0x7FFFFFFFu);
        float4 B = cb[pos];
        float a1 = (B.z - B.x) * (B.w - B.y);

        // ---- suppression (selected box suppresses itself, IoU = 1) ----
        for (int i = tid; i < M; i += NMS_T) {
            if (s_key[i]) {
                float4 C = cb[i];
                float ty  = fmaxf(B.x, C.x);
                float tx  = fmaxf(B.y, C.y);
                float by  = fminf(B.z, C.z);
                float bxr = fminf(B.w, C.w);
                float hh  = fmaxf(by - ty, 0.f);
                float ww  = fmaxf(bxr - tx, 0.f);
                float inter = hh * ww;
                float a2 = (C.z - C.x) * (C.w - C.y);
                float iou = inter / (a1 + a2 - inter + 1e-12f);
                if (iou > 0.5f) s_key[i] = 0ull;
            }
        }

        if (tid == 0) {
            float* o = out + ((size_t)b * MAXOUT + t) * 6;
            o[0] = B.x; o[1] = B.y; o[2] = B.z; o[3] = B.w;
            o[4] = g_ccls[(size_t)b * NANCH + pos];
            o[5] = sc;
        }
        __syncthreads();
    }
}

// ---------------------------------------------------------------------------
extern "C" void kernel_launch(void* const* d_in, const int* in_sizes, int n_in,
                              void* d_out, int out_size) {
    const float* logits = (const float*)d_in[0];   // [128, 8732, 25]
    const float* db     = (const float*)d_in[1];   // [8732, 4]
    float*       out    = (float*)d_out;           // [128, 5, 6]

    decode_kernel<<<BATCH * NANCH / DEC_T, DEC_T>>>(logits, db);
    nms_kernel<<<BATCH, NMS_T>>>(out);
}